// round 15
// baseline (speedup 1.0000x reference)
#include <cuda_runtime.h>
#include <cuda_fp16.h>
#include <cstdint>

// ---------------------------------------------------------------------------
// LoRALinear (sm_103 base-target safe — NO tcgen05):
//   1) prep: g_xh = fp16_rn(x); g_wh = fp16_rn(W + (alpha/r)*B@A)  (one launch)
//   2) gemm: out = g_xh @ g_wh^T + bias via mma.sync.m16n8k16 (fp32 accum)
// R14 skeleton: CTA 128x128, 8 warps (64x32), BK=64, 3-stage cp.async ring,
// 2 CTAs/SM, single __syncthreads/iter, GROUP_M=16 block swizzle.
// R15 delta: explicit double-buffered fragments — LDSM for ks+1 issued before
// the MMA burst of ks, hiding LDSM latency under tensor work.
// ---------------------------------------------------------------------------

constexpr int M_TOT = 16384;
constexpr int N_TOT = 4096;
constexpr int K_TOT = 4096;
constexpr int RANK  = 16;
constexpr float LSCALE = 1.0f;     // alpha / max(1,r) = 16/16

__device__ __half g_xh[(size_t)M_TOT * (size_t)K_TOT];
__device__ __half g_wh[(size_t)N_TOT * (size_t)K_TOT];

// ---------------- helpers ----------------
__device__ __forceinline__ uint32_t smem_u32(const void* p) {
    return (uint32_t)__cvta_generic_to_shared(p);
}
__device__ __forceinline__ void cp_async16(uint32_t s, const void* g) {
    asm volatile("cp.async.cg.shared.global [%0], [%1], 16;" :: "r"(s), "l"(g) : "memory");
}
__device__ __forceinline__ void cp_commit() {
    asm volatile("cp.async.commit_group;" ::: "memory");
}
template <int N> __device__ __forceinline__ void cp_wait() {
    asm volatile("cp.async.wait_group %0;" :: "n"(N) : "memory");
}

// ---------------- kernel 1: prep (conv x || fold W) ----------------
constexpr int CONV_BLOCKS = 8192;
constexpr int FOLD_BLOCKS = 4096;

__global__ void prep_kernel(const float4* __restrict__ X,
                            const float* __restrict__ W,
                            const float* __restrict__ lA,
                            const float* __restrict__ lB) {
    int b = blockIdx.x;
    if (b < CONV_BLOCKS) {
        size_t n4 = (size_t)M_TOT * K_TOT / 4;
        uint2* o = reinterpret_cast<uint2*>(g_xh);
        for (size_t i = (size_t)b * blockDim.x + threadIdx.x; i < n4;
             i += (size_t)CONV_BLOCKS * blockDim.x) {
            float4 v = X[i];
            __half2 h0 = __floats2half2_rn(v.x, v.y);
            __half2 h1 = __floats2half2_rn(v.z, v.w);
            o[i] = make_uint2(*reinterpret_cast<uint32_t*>(&h0),
                              *reinterpret_cast<uint32_t*>(&h1));
        }
    } else {
        int fb = b - CONV_BLOCKS;
        int total4 = N_TOT * K_TOT / 4;
        uint2* out = reinterpret_cast<uint2*>(g_wh);
        for (int idx = fb * blockDim.x + threadIdx.x; idx < total4;
             idx += FOLD_BLOCKS * blockDim.x) {
            int o  = idx / (K_TOT / 4);
            int i4 = idx % (K_TOT / 4);
            float4 w = reinterpret_cast<const float4*>(W)[idx];
            #pragma unroll
            for (int r = 0; r < RANK; r++) {
                float  bb = __ldg(&lB[o * RANK + r]) * LSCALE;
                float4 a = reinterpret_cast<const float4*>(lA)[r * (K_TOT / 4) + i4];
                w.x += bb * a.x; w.y += bb * a.y; w.z += bb * a.z; w.w += bb * a.w;
            }
            __half2 h0 = __floats2half2_rn(w.x, w.y);
            __half2 h1 = __floats2half2_rn(w.z, w.w);
            out[idx] = make_uint2(*reinterpret_cast<uint32_t*>(&h0),
                                  *reinterpret_cast<uint32_t*>(&h1));
        }
    }
}

// ---------------- kernel 2: fp16 tensor-core GEMM ----------------
constexpr int BM = 128, BN = 128, BK = 64;   // BK halfs = 128 B row
constexpr int A_BYTES   = BM * BK * 2;       // 16384
constexpr int B_BYTES   = BN * BK * 2;       // 16384
constexpr int STG_BYTES = A_BYTES + B_BYTES; // 32768
constexpr int SMEM_BYTES = 3 * STG_BYTES;    // 98304
constexpr int KT = K_TOT / BK;               // 64
constexpr int THREADS = 256;
constexpr int MT = M_TOT / BM;               // 128
constexpr int NT = N_TOT / BN;               // 32
constexpr int GROUP_M = 16;                  // m-tiles per panel

__device__ __forceinline__ uint32_t sw128(uint32_t off) {
    return off ^ ((off >> 3) & 0x70);
}

__device__ __forceinline__ void load_stage(uint32_t base, int q, int m0, int n0,
                                           int tid) {
    const uint32_t s = (uint32_t)q % 3u;
    const int k0 = q * BK;
    const uint32_t abase = base + s * STG_BYTES;
    const uint32_t bbase = abase + A_BYTES;
    #pragma unroll
    for (int i = 0; i < 4; i++) {            // A: 1024 x 16B
        int c = tid + i * THREADS;
        int row = c >> 3, kc = c & 7;
        cp_async16(abase + sw128((uint32_t)(row * 128 + kc * 16)),
                   &g_xh[(size_t)(m0 + row) * K_TOT + k0 + kc * 8]);
    }
    #pragma unroll
    for (int i = 0; i < 4; i++) {            // B: 1024 x 16B
        int c = tid + i * THREADS;
        int row = c >> 3, kc = c & 7;
        cp_async16(bbase + sw128((uint32_t)(row * 128 + kc * 16)),
                   &g_wh[(size_t)(n0 + row) * K_TOT + k0 + kc * 8]);
    }
}

__global__ __launch_bounds__(THREADS, 2)
void gemm_kernel(const float* __restrict__ bias, float* __restrict__ Out) {
    extern __shared__ char smraw[];
    const uint32_t base = smem_u32(smraw);

    const int tid  = threadIdx.x;
    const int lane = tid & 31;
    const int warp = tid >> 5;
    const int wm = (warp >> 2) * 64;         // 0 / 64
    const int wn = (warp & 3) * 32;          // 0..96

    // GROUP_M block swizzle: consecutive blockIdx sweep 16 m-tiles, then n.
    const int t     = blockIdx.x;
    const int local = t & (GROUP_M * NT - 1);       // within panel (512)
    const int mt    = ((t >> 9) << 4) + (local & (GROUP_M - 1));
    const int nt    = local >> 4;
    const int m0    = mt * BM;
    const int n0    = nt * BN;

    // precomputed per-thread swizzled smem byte offsets (ks folds in via XOR)
    const int a_row  = (lane & 15);
    const int a_koff = (lane >> 4) * 16;
    const int b_row  = ((lane >> 4) << 3) + (lane & 7);
    const int b_koff = ((lane >> 3) & 1) * 16;
    uint32_t swa[4], swb[2];
    #pragma unroll
    for (int i = 0; i < 4; i++)
        swa[i] = sw128((uint32_t)((wm + i * 16 + a_row) * 128 + a_koff));
    #pragma unroll
    for (int j2 = 0; j2 < 2; j2++)
        swb[j2] = sw128((uint32_t)((wn + j2 * 16 + b_row) * 128 + b_koff));

    float acc[4][4][4];
    #pragma unroll
    for (int i = 0; i < 4; i++)
        #pragma unroll
        for (int j = 0; j < 4; j++)
            #pragma unroll
            for (int q = 0; q < 4; q++) acc[i][j][q] = 0.f;

    load_stage(base, 0, m0, n0, tid); cp_commit();
    load_stage(base, 1, m0, n0, tid); cp_commit();

    uint32_t a[2][4][4];                     // double-buffered fragments
    uint32_t b[2][2][4];

    uint32_t cur = 0;                        // stage index of tile kt
    for (int kt = 0; kt < KT; kt++) {
        if (kt + 1 < KT) cp_wait<1>();       // stage kt resident
        else             cp_wait<0>();
        __syncthreads();                     // also fences stage reuse

        const uint32_t abase = base + cur * STG_BYTES;
        const uint32_t bbase = abase + A_BYTES;

        // preload ks=0 fragments into buffer 0
        #pragma unroll
        for (int i = 0; i < 4; i++)
            asm volatile(
                "ldmatrix.sync.aligned.m8n8.x4.shared.b16 {%0,%1,%2,%3}, [%4];"
                : "=r"(a[0][i][0]), "=r"(a[0][i][1]),
                  "=r"(a[0][i][2]), "=r"(a[0][i][3])
                : "r"(abase + swa[i]));
        #pragma unroll
        for (int j2 = 0; j2 < 2; j2++)
            asm volatile(
                "ldmatrix.sync.aligned.m8n8.x4.shared.b16 {%0,%1,%2,%3}, [%4];"
                : "=r"(b[0][j2][0]), "=r"(b[0][j2][1]),
                  "=r"(b[0][j2][2]), "=r"(b[0][j2][3])
                : "r"(bbase + swb[j2]));

        #pragma unroll
        for (int ks = 0; ks < 4; ks++) {     // 4 x k16 per stage
            const int buf  = ks & 1;
            const int nbuf = buf ^ 1;
            if (ks < 3) {                    // LDSM ks+1 before MMA burst of ks
                const uint32_t kx = (uint32_t)((ks + 1) * 32);
                #pragma unroll
                for (int i = 0; i < 4; i++)
                    asm volatile(
                        "ldmatrix.sync.aligned.m8n8.x4.shared.b16 {%0,%1,%2,%3}, [%4];"
                        : "=r"(a[nbuf][i][0]), "=r"(a[nbuf][i][1]),
                          "=r"(a[nbuf][i][2]), "=r"(a[nbuf][i][3])
                        : "r"(abase + (swa[i] ^ kx)));
                #pragma unroll
                for (int j2 = 0; j2 < 2; j2++)
                    asm volatile(
                        "ldmatrix.sync.aligned.m8n8.x4.shared.b16 {%0,%1,%2,%3}, [%4];"
                        : "=r"(b[nbuf][j2][0]), "=r"(b[nbuf][j2][1]),
                          "=r"(b[nbuf][j2][2]), "=r"(b[nbuf][j2][3])
                        : "r"(bbase + (swb[j2] ^ kx)));
            }
            #pragma unroll
            for (int i = 0; i < 4; i++)
                #pragma unroll
                for (int j = 0; j < 4; j++) {
                    asm volatile(
                        "mma.sync.aligned.m16n8k16.row.col.f32.f16.f16.f32 "
                        "{%0,%1,%2,%3}, {%4,%5,%6,%7}, {%8,%9}, {%0,%1,%2,%3};"
                        : "+f"(acc[i][j][0]), "+f"(acc[i][j][1]),
                          "+f"(acc[i][j][2]), "+f"(acc[i][j][3])
                        : "r"(a[buf][i][0]), "r"(a[buf][i][1]),
                          "r"(a[buf][i][2]), "r"(a[buf][i][3]),
                          "r"(b[buf][j >> 1][(j & 1) * 2]),
                          "r"(b[buf][j >> 1][(j & 1) * 2 + 1]));
                }
            if (ks == 0 && kt + 2 < KT) {    // compact prefetch burst
                load_stage(base, kt + 2, m0, n0, tid);
                cp_commit();
            }
        }
        cur = (cur == 2) ? 0 : cur + 1;
    }

    // Epilogue: += bias, write out
    const int row0 = m0 + wm + (lane >> 2);
    const int col0 = n0 + wn + ((lane & 3) << 1);
    float2 bv[4];
    #pragma unroll
    for (int j = 0; j < 4; j++)
        bv[j] = *reinterpret_cast<const float2*>(&bias[col0 + j * 8]);
    #pragma unroll
    for (int i = 0; i < 4; i++) {
        #pragma unroll
        for (int j = 0; j < 4; j++) {
            int r = row0 + i * 16;
            int c = col0 + j * 8;
            float2 v0 = make_float2(acc[i][j][0] + bv[j].x, acc[i][j][1] + bv[j].y);
            float2 v1 = make_float2(acc[i][j][2] + bv[j].x, acc[i][j][3] + bv[j].y);
            *reinterpret_cast<float2*>(&Out[(size_t)r * N_TOT + c])       = v0;
            *reinterpret_cast<float2*>(&Out[(size_t)(r + 8) * N_TOT + c]) = v1;
        }
    }
}

// ---------------- launch ----------------
extern "C" void kernel_launch(void* const* d_in, const int* in_sizes, int n_in,
                              void* d_out, int out_size) {
    const float* x    = (const float*)d_in[0];
    const float* W    = (const float*)d_in[1];
    const float* bias = (const float*)d_in[2];
    const float* lA   = (const float*)d_in[3];
    const float* lB   = (const float*)d_in[4];
    float* out = (float*)d_out;
    (void)in_sizes; (void)n_in; (void)out_size;

    prep_kernel<<<CONV_BLOCKS + FOLD_BLOCKS, 256>>>(
        reinterpret_cast<const float4*>(x), W, lA, lB);

    cudaFuncSetAttribute(gemm_kernel,
                         cudaFuncAttributeMaxDynamicSharedMemorySize, SMEM_BYTES);
    gemm_kernel<<<MT * NT, THREADS, SMEM_BYTES>>>(bias, out);
}

// round 16
// speedup vs baseline: 1.6368x; 1.6368x over previous
#include <cuda_runtime.h>
#include <cuda_fp16.h>
#include <cstdint>

// ---------------------------------------------------------------------------
// LoRALinear (sm_103 base-target safe — NO tcgen05):
//   1) prep: g_xh = fp16_rn(x); g_wh = fp16_rn(W + (alpha/r)*B@A)  (one launch)
//   2) gemm: out = g_xh @ g_wh^T + bias via mma.sync.m16n8k16 (fp32 accum)
// R14 skeleton: CTA 128x128, 8 warps (64x32), BK=64, 3-stage cp.async ring,
// 2 CTAs/SM, single __syncthreads/iter, GROUP_M=16 block swizzle.
// R16 delta: odd CTAs rotate the k-chunk order by 32 (modular) to decorrelate
// the two co-resident CTAs' barrier phases (zero extra registers).
// ---------------------------------------------------------------------------

constexpr int M_TOT = 16384;
constexpr int N_TOT = 4096;
constexpr int K_TOT = 4096;
constexpr int RANK  = 16;
constexpr float LSCALE = 1.0f;     // alpha / max(1,r) = 16/16

__device__ __half g_xh[(size_t)M_TOT * (size_t)K_TOT];
__device__ __half g_wh[(size_t)N_TOT * (size_t)K_TOT];

// ---------------- helpers ----------------
__device__ __forceinline__ uint32_t smem_u32(const void* p) {
    return (uint32_t)__cvta_generic_to_shared(p);
}
__device__ __forceinline__ void cp_async16(uint32_t s, const void* g) {
    asm volatile("cp.async.cg.shared.global [%0], [%1], 16;" :: "r"(s), "l"(g) : "memory");
}
__device__ __forceinline__ void cp_commit() {
    asm volatile("cp.async.commit_group;" ::: "memory");
}
template <int N> __device__ __forceinline__ void cp_wait() {
    asm volatile("cp.async.wait_group %0;" :: "n"(N) : "memory");
}

// ---------------- kernel 1: prep (conv x || fold W) ----------------
constexpr int CONV_BLOCKS = 8192;
constexpr int FOLD_BLOCKS = 4096;

__global__ void prep_kernel(const float4* __restrict__ X,
                            const float* __restrict__ W,
                            const float* __restrict__ lA,
                            const float* __restrict__ lB) {
    int b = blockIdx.x;
    if (b < CONV_BLOCKS) {
        size_t n4 = (size_t)M_TOT * K_TOT / 4;
        uint2* o = reinterpret_cast<uint2*>(g_xh);
        for (size_t i = (size_t)b * blockDim.x + threadIdx.x; i < n4;
             i += (size_t)CONV_BLOCKS * blockDim.x) {
            float4 v = X[i];
            __half2 h0 = __floats2half2_rn(v.x, v.y);
            __half2 h1 = __floats2half2_rn(v.z, v.w);
            o[i] = make_uint2(*reinterpret_cast<uint32_t*>(&h0),
                              *reinterpret_cast<uint32_t*>(&h1));
        }
    } else {
        int fb = b - CONV_BLOCKS;
        int total4 = N_TOT * K_TOT / 4;
        uint2* out = reinterpret_cast<uint2*>(g_wh);
        for (int idx = fb * blockDim.x + threadIdx.x; idx < total4;
             idx += FOLD_BLOCKS * blockDim.x) {
            int o  = idx / (K_TOT / 4);
            int i4 = idx % (K_TOT / 4);
            float4 w = reinterpret_cast<const float4*>(W)[idx];
            #pragma unroll
            for (int r = 0; r < RANK; r++) {
                float  bb = __ldg(&lB[o * RANK + r]) * LSCALE;
                float4 a = reinterpret_cast<const float4*>(lA)[r * (K_TOT / 4) + i4];
                w.x += bb * a.x; w.y += bb * a.y; w.z += bb * a.z; w.w += bb * a.w;
            }
            __half2 h0 = __floats2half2_rn(w.x, w.y);
            __half2 h1 = __floats2half2_rn(w.z, w.w);
            out[idx] = make_uint2(*reinterpret_cast<uint32_t*>(&h0),
                                  *reinterpret_cast<uint32_t*>(&h1));
        }
    }
}

// ---------------- kernel 2: fp16 tensor-core GEMM ----------------
constexpr int BM = 128, BN = 128, BK = 64;   // BK halfs = 128 B row
constexpr int A_BYTES   = BM * BK * 2;       // 16384
constexpr int B_BYTES   = BN * BK * 2;       // 16384
constexpr int STG_BYTES = A_BYTES + B_BYTES; // 32768
constexpr int SMEM_BYTES = 3 * STG_BYTES;    // 98304
constexpr int KT = K_TOT / BK;               // 64
constexpr int THREADS = 256;
constexpr int MT = M_TOT / BM;               // 128
constexpr int NT = N_TOT / BN;               // 32
constexpr int GROUP_M = 16;                  // m-tiles per panel

__device__ __forceinline__ uint32_t sw128(uint32_t off) {
    return off ^ ((off >> 3) & 0x70);
}

// q = pipeline slot index (for stage selection), kk = k-chunk to load
__device__ __forceinline__ void load_stage(uint32_t base, int q, int kk,
                                           int m0, int n0, int tid) {
    const uint32_t s = (uint32_t)q % 3u;
    const int k0 = kk * BK;
    const uint32_t abase = base + s * STG_BYTES;
    const uint32_t bbase = abase + A_BYTES;
    #pragma unroll
    for (int i = 0; i < 4; i++) {            // A: 1024 x 16B
        int c = tid + i * THREADS;
        int row = c >> 3, kc = c & 7;
        cp_async16(abase + sw128((uint32_t)(row * 128 + kc * 16)),
                   &g_xh[(size_t)(m0 + row) * K_TOT + k0 + kc * 8]);
    }
    #pragma unroll
    for (int i = 0; i < 4; i++) {            // B: 1024 x 16B
        int c = tid + i * THREADS;
        int row = c >> 3, kc = c & 7;
        cp_async16(bbase + sw128((uint32_t)(row * 128 + kc * 16)),
                   &g_wh[(size_t)(n0 + row) * K_TOT + k0 + kc * 8]);
    }
}

__global__ __launch_bounds__(THREADS, 2)
void gemm_kernel(const float* __restrict__ bias, float* __restrict__ Out) {
    extern __shared__ char smraw[];
    const uint32_t base = smem_u32(smraw);

    const int tid  = threadIdx.x;
    const int lane = tid & 31;
    const int warp = tid >> 5;
    const int wm = (warp >> 2) * 64;         // 0 / 64
    const int wn = (warp & 3) * 32;          // 0..96

    // GROUP_M block swizzle: consecutive blockIdx sweep 16 m-tiles, then n.
    const int t     = blockIdx.x;
    const int local = t & (GROUP_M * NT - 1);       // within panel (512)
    const int mt    = ((t >> 9) << 4) + (local & (GROUP_M - 1));
    const int nt    = local >> 4;
    const int m0    = mt * BM;
    const int n0    = nt * BN;

    // k-chunk rotation: odd CTAs start at chunk 32 -> decorrelates the two
    // co-resident CTAs' memory/barrier phases. All 64 chunks still covered.
    const int kstart = (t & 1) << 5;

    // precomputed per-thread swizzled smem byte offsets (ks folds in via XOR)
    const int a_row  = (lane & 15);
    const int a_koff = (lane >> 4) * 16;
    const int b_row  = ((lane >> 4) << 3) + (lane & 7);
    const int b_koff = ((lane >> 3) & 1) * 16;
    uint32_t swa[4], swb[2];
    #pragma unroll
    for (int i = 0; i < 4; i++)
        swa[i] = sw128((uint32_t)((wm + i * 16 + a_row) * 128 + a_koff));
    #pragma unroll
    for (int j2 = 0; j2 < 2; j2++)
        swb[j2] = sw128((uint32_t)((wn + j2 * 16 + b_row) * 128 + b_koff));

    float acc[4][4][4];
    #pragma unroll
    for (int i = 0; i < 4; i++)
        #pragma unroll
        for (int j = 0; j < 4; j++)
            #pragma unroll
            for (int q = 0; q < 4; q++) acc[i][j][q] = 0.f;

    load_stage(base, 0, kstart,            m0, n0, tid); cp_commit();
    load_stage(base, 1, (kstart + 1) & 63, m0, n0, tid); cp_commit();

    uint32_t cur = 0;                        // stage index of iteration kt
    for (int kt = 0; kt < KT; kt++) {
        if (kt + 1 < KT) cp_wait<1>();       // stage kt resident
        else             cp_wait<0>();
        __syncthreads();                     // also fences stage reuse

        const uint32_t abase = base + cur * STG_BYTES;
        const uint32_t bbase = abase + A_BYTES;

        #pragma unroll
        for (int ks = 0; ks < 4; ks++) {     // 4 x k16 per stage
            const uint32_t kx = (uint32_t)(ks * 32);
            uint32_t a[4][4];
            #pragma unroll
            for (int i = 0; i < 4; i++) {
                asm volatile(
                    "ldmatrix.sync.aligned.m8n8.x4.shared.b16 {%0,%1,%2,%3}, [%4];"
                    : "=r"(a[i][0]), "=r"(a[i][1]), "=r"(a[i][2]), "=r"(a[i][3])
                    : "r"(abase + (swa[i] ^ kx)));
            }
            uint32_t b[2][4];                // b[j2] covers n-tiles 2*j2, 2*j2+1
            #pragma unroll
            for (int j2 = 0; j2 < 2; j2++) {
                asm volatile(
                    "ldmatrix.sync.aligned.m8n8.x4.shared.b16 {%0,%1,%2,%3}, [%4];"
                    : "=r"(b[j2][0]), "=r"(b[j2][1]), "=r"(b[j2][2]), "=r"(b[j2][3])
                    : "r"(bbase + (swb[j2] ^ kx)));
            }
            #pragma unroll
            for (int i = 0; i < 4; i++)
                #pragma unroll
                for (int j = 0; j < 4; j++) {
                    asm volatile(
                        "mma.sync.aligned.m16n8k16.row.col.f32.f16.f16.f32 "
                        "{%0,%1,%2,%3}, {%4,%5,%6,%7}, {%8,%9}, {%0,%1,%2,%3};"
                        : "+f"(acc[i][j][0]), "+f"(acc[i][j][1]),
                          "+f"(acc[i][j][2]), "+f"(acc[i][j][3])
                        : "r"(a[i][0]), "r"(a[i][1]), "r"(a[i][2]), "r"(a[i][3]),
                          "r"(b[j >> 1][(j & 1) * 2]), "r"(b[j >> 1][(j & 1) * 2 + 1]));
                }
            if (ks == 0 && kt + 2 < KT) {    // compact prefetch burst
                load_stage(base, kt + 2, (kt + 2 + kstart) & 63, m0, n0, tid);
                cp_commit();
            }
        }
        cur = (cur == 2) ? 0 : cur + 1;
    }

    // Epilogue: += bias, write out
    const int row0 = m0 + wm + (lane >> 2);
    const int col0 = n0 + wn + ((lane & 3) << 1);
    float2 bv[4];
    #pragma unroll
    for (int j = 0; j < 4; j++)
        bv[j] = *reinterpret_cast<const float2*>(&bias[col0 + j * 8]);
    #pragma unroll
    for (int i = 0; i < 4; i++) {
        #pragma unroll
        for (int j = 0; j < 4; j++) {
            int r = row0 + i * 16;
            int c = col0 + j * 8;
            float2 v0 = make_float2(acc[i][j][0] + bv[j].x, acc[i][j][1] + bv[j].y);
            float2 v1 = make_float2(acc[i][j][2] + bv[j].x, acc[i][j][3] + bv[j].y);
            *reinterpret_cast<float2*>(&Out[(size_t)r * N_TOT + c])       = v0;
            *reinterpret_cast<float2*>(&Out[(size_t)(r + 8) * N_TOT + c]) = v1;
        }
    }
}

// ---------------- launch ----------------
extern "C" void kernel_launch(void* const* d_in, const int* in_sizes, int n_in,
                              void* d_out, int out_size) {
    const float* x    = (const float*)d_in[0];
    const float* W    = (const float*)d_in[1];
    const float* bias = (const float*)d_in[2];
    const float* lA   = (const float*)d_in[3];
    const float* lB   = (const float*)d_in[4];
    float* out = (float*)d_out;
    (void)in_sizes; (void)n_in; (void)out_size;

    prep_kernel<<<CONV_BLOCKS + FOLD_BLOCKS, 256>>>(
        reinterpret_cast<const float4*>(x), W, lA, lB);

    cudaFuncSetAttribute(gemm_kernel,
                         cudaFuncAttributeMaxDynamicSharedMemorySize, SMEM_BYTES);
    gemm_kernel<<<MT * NT, THREADS, SMEM_BYTES>>>(bias, out);
}

// round 17
// speedup vs baseline: 1.6370x; 1.0001x over previous
#include <cuda_runtime.h>
#include <cuda_fp16.h>
#include <cstdint>

// ---------------------------------------------------------------------------
// LoRALinear (sm_103 base-target safe — NO tcgen05):
//   1) prep: g_xh = fp16_rn(x); g_wh = fp16_rn(W + (alpha/r)*B@A)  (one launch)
//   2) gemm: out = g_xh @ g_wh^T + bias via mma.sync.m16n8k16 (fp32 accum)
// R14 skeleton: CTA 128x128, 8 warps (64x32), BK=64, 3-stage cp.async ring,
// 2 CTAs/SM, single __syncthreads/iter, GROUP_M=16 block swizzle.
// R17 delta: 4-phase k-chunk rotation keyed to bit2 (co-resident CTA pairs
// differ by 148 -> bit2 always flips) + bit0 (neighbor SMs). Anti-phases the
// two CTAs sharing an SM at zero register cost.
// ---------------------------------------------------------------------------

constexpr int M_TOT = 16384;
constexpr int N_TOT = 4096;
constexpr int K_TOT = 4096;
constexpr int RANK  = 16;
constexpr float LSCALE = 1.0f;     // alpha / max(1,r) = 16/16

__device__ __half g_xh[(size_t)M_TOT * (size_t)K_TOT];
__device__ __half g_wh[(size_t)N_TOT * (size_t)K_TOT];

// ---------------- helpers ----------------
__device__ __forceinline__ uint32_t smem_u32(const void* p) {
    return (uint32_t)__cvta_generic_to_shared(p);
}
__device__ __forceinline__ void cp_async16(uint32_t s, const void* g) {
    asm volatile("cp.async.cg.shared.global [%0], [%1], 16;" :: "r"(s), "l"(g) : "memory");
}
__device__ __forceinline__ void cp_commit() {
    asm volatile("cp.async.commit_group;" ::: "memory");
}
template <int N> __device__ __forceinline__ void cp_wait() {
    asm volatile("cp.async.wait_group %0;" :: "n"(N) : "memory");
}

// ---------------- kernel 1: prep (conv x || fold W) ----------------
constexpr int CONV_BLOCKS = 8192;
constexpr int FOLD_BLOCKS = 4096;

__global__ void prep_kernel(const float4* __restrict__ X,
                            const float* __restrict__ W,
                            const float* __restrict__ lA,
                            const float* __restrict__ lB) {
    int b = blockIdx.x;
    if (b < CONV_BLOCKS) {
        size_t n4 = (size_t)M_TOT * K_TOT / 4;
        uint2* o = reinterpret_cast<uint2*>(g_xh);
        for (size_t i = (size_t)b * blockDim.x + threadIdx.x; i < n4;
             i += (size_t)CONV_BLOCKS * blockDim.x) {
            float4 v = X[i];
            __half2 h0 = __floats2half2_rn(v.x, v.y);
            __half2 h1 = __floats2half2_rn(v.z, v.w);
            o[i] = make_uint2(*reinterpret_cast<uint32_t*>(&h0),
                              *reinterpret_cast<uint32_t*>(&h1));
        }
    } else {
        int fb = b - CONV_BLOCKS;
        int total4 = N_TOT * K_TOT / 4;
        uint2* out = reinterpret_cast<uint2*>(g_wh);
        for (int idx = fb * blockDim.x + threadIdx.x; idx < total4;
             idx += FOLD_BLOCKS * blockDim.x) {
            int o  = idx / (K_TOT / 4);
            int i4 = idx % (K_TOT / 4);
            float4 w = reinterpret_cast<const float4*>(W)[idx];
            #pragma unroll
            for (int r = 0; r < RANK; r++) {
                float  bb = __ldg(&lB[o * RANK + r]) * LSCALE;
                float4 a = reinterpret_cast<const float4*>(lA)[r * (K_TOT / 4) + i4];
                w.x += bb * a.x; w.y += bb * a.y; w.z += bb * a.z; w.w += bb * a.w;
            }
            __half2 h0 = __floats2half2_rn(w.x, w.y);
            __half2 h1 = __floats2half2_rn(w.z, w.w);
            out[idx] = make_uint2(*reinterpret_cast<uint32_t*>(&h0),
                                  *reinterpret_cast<uint32_t*>(&h1));
        }
    }
}

// ---------------- kernel 2: fp16 tensor-core GEMM ----------------
constexpr int BM = 128, BN = 128, BK = 64;   // BK halfs = 128 B row
constexpr int A_BYTES   = BM * BK * 2;       // 16384
constexpr int B_BYTES   = BN * BK * 2;       // 16384
constexpr int STG_BYTES = A_BYTES + B_BYTES; // 32768
constexpr int SMEM_BYTES = 3 * STG_BYTES;    // 98304
constexpr int KT = K_TOT / BK;               // 64
constexpr int THREADS = 256;
constexpr int MT = M_TOT / BM;               // 128
constexpr int NT = N_TOT / BN;               // 32
constexpr int GROUP_M = 16;                  // m-tiles per panel

__device__ __forceinline__ uint32_t sw128(uint32_t off) {
    return off ^ ((off >> 3) & 0x70);
}

// q = pipeline slot index (for stage selection), kk = k-chunk to load
__device__ __forceinline__ void load_stage(uint32_t base, int q, int kk,
                                           int m0, int n0, int tid) {
    const uint32_t s = (uint32_t)q % 3u;
    const int k0 = kk * BK;
    const uint32_t abase = base + s * STG_BYTES;
    const uint32_t bbase = abase + A_BYTES;
    #pragma unroll
    for (int i = 0; i < 4; i++) {            // A: 1024 x 16B
        int c = tid + i * THREADS;
        int row = c >> 3, kc = c & 7;
        cp_async16(abase + sw128((uint32_t)(row * 128 + kc * 16)),
                   &g_xh[(size_t)(m0 + row) * K_TOT + k0 + kc * 8]);
    }
    #pragma unroll
    for (int i = 0; i < 4; i++) {            // B: 1024 x 16B
        int c = tid + i * THREADS;
        int row = c >> 3, kc = c & 7;
        cp_async16(bbase + sw128((uint32_t)(row * 128 + kc * 16)),
                   &g_wh[(size_t)(n0 + row) * K_TOT + k0 + kc * 8]);
    }
}

__global__ __launch_bounds__(THREADS, 2)
void gemm_kernel(const float* __restrict__ bias, float* __restrict__ Out) {
    extern __shared__ char smraw[];
    const uint32_t base = smem_u32(smraw);

    const int tid  = threadIdx.x;
    const int lane = tid & 31;
    const int warp = tid >> 5;
    const int wm = (warp >> 2) * 64;         // 0 / 64
    const int wn = (warp & 3) * 32;          // 0..96

    // GROUP_M block swizzle: consecutive blockIdx sweep 16 m-tiles, then n.
    const int t     = blockIdx.x;
    const int local = t & (GROUP_M * NT - 1);       // within panel (512)
    const int mt    = ((t >> 9) << 4) + (local & (GROUP_M - 1));
    const int nt    = local >> 4;
    const int m0    = mt * BM;
    const int n0    = nt * BN;

    // 4-phase k-chunk rotation: co-resident CTA pairs differ by 148 -> bit 2
    // always flips (bits 0-1 of 148 are zero), so bit2 anti-phases the two
    // CTAs sharing an SM by 32 chunks; bit0 spreads neighbor SMs by 16.
    const int kstart = (((t >> 2) & 1) << 5) | ((t & 1) << 4);

    // precomputed per-thread swizzled smem byte offsets (ks folds in via XOR)
    const int a_row  = (lane & 15);
    const int a_koff = (lane >> 4) * 16;
    const int b_row  = ((lane >> 4) << 3) + (lane & 7);
    const int b_koff = ((lane >> 3) & 1) * 16;
    uint32_t swa[4], swb[2];
    #pragma unroll
    for (int i = 0; i < 4; i++)
        swa[i] = sw128((uint32_t)((wm + i * 16 + a_row) * 128 + a_koff));
    #pragma unroll
    for (int j2 = 0; j2 < 2; j2++)
        swb[j2] = sw128((uint32_t)((wn + j2 * 16 + b_row) * 128 + b_koff));

    float acc[4][4][4];
    #pragma unroll
    for (int i = 0; i < 4; i++)
        #pragma unroll
        for (int j = 0; j < 4; j++)
            #pragma unroll
            for (int q = 0; q < 4; q++) acc[i][j][q] = 0.f;

    load_stage(base, 0, kstart,            m0, n0, tid); cp_commit();
    load_stage(base, 1, (kstart + 1) & 63, m0, n0, tid); cp_commit();

    uint32_t cur = 0;                        // stage index of iteration kt
    for (int kt = 0; kt < KT; kt++) {
        if (kt + 1 < KT) cp_wait<1>();       // stage kt resident
        else             cp_wait<0>();
        __syncthreads();                     // also fences stage reuse

        const uint32_t abase = base + cur * STG_BYTES;
        const uint32_t bbase = abase + A_BYTES;

        #pragma unroll
        for (int ks = 0; ks < 4; ks++) {     // 4 x k16 per stage
            const uint32_t kx = (uint32_t)(ks * 32);
            uint32_t a[4][4];
            #pragma unroll
            for (int i = 0; i < 4; i++) {
                asm volatile(
                    "ldmatrix.sync.aligned.m8n8.x4.shared.b16 {%0,%1,%2,%3}, [%4];"
                    : "=r"(a[i][0]), "=r"(a[i][1]), "=r"(a[i][2]), "=r"(a[i][3])
                    : "r"(abase + (swa[i] ^ kx)));
            }
            uint32_t b[2][4];                // b[j2] covers n-tiles 2*j2, 2*j2+1
            #pragma unroll
            for (int j2 = 0; j2 < 2; j2++) {
                asm volatile(
                    "ldmatrix.sync.aligned.m8n8.x4.shared.b16 {%0,%1,%2,%3}, [%4];"
                    : "=r"(b[j2][0]), "=r"(b[j2][1]), "=r"(b[j2][2]), "=r"(b[j2][3])
                    : "r"(bbase + (swb[j2] ^ kx)));
            }
            #pragma unroll
            for (int i = 0; i < 4; i++)
                #pragma unroll
                for (int j = 0; j < 4; j++) {
                    asm volatile(
                        "mma.sync.aligned.m16n8k16.row.col.f32.f16.f16.f32 "
                        "{%0,%1,%2,%3}, {%4,%5,%6,%7}, {%8,%9}, {%0,%1,%2,%3};"
                        : "+f"(acc[i][j][0]), "+f"(acc[i][j][1]),
                          "+f"(acc[i][j][2]), "+f"(acc[i][j][3])
                        : "r"(a[i][0]), "r"(a[i][1]), "r"(a[i][2]), "r"(a[i][3]),
                          "r"(b[j >> 1][(j & 1) * 2]), "r"(b[j >> 1][(j & 1) * 2 + 1]));
                }
            if (ks == 0 && kt + 2 < KT) {    // compact prefetch burst
                load_stage(base, kt + 2, (kt + 2 + kstart) & 63, m0, n0, tid);
                cp_commit();
            }
        }
        cur = (cur == 2) ? 0 : cur + 1;
    }

    // Epilogue: += bias, write out
    const int row0 = m0 + wm + (lane >> 2);
    const int col0 = n0 + wn + ((lane & 3) << 1);
    float2 bv[4];
    #pragma unroll
    for (int j = 0; j < 4; j++)
        bv[j] = *reinterpret_cast<const float2*>(&bias[col0 + j * 8]);
    #pragma unroll
    for (int i = 0; i < 4; i++) {
        #pragma unroll
        for (int j = 0; j < 4; j++) {
            int r = row0 + i * 16;
            int c = col0 + j * 8;
            float2 v0 = make_float2(acc[i][j][0] + bv[j].x, acc[i][j][1] + bv[j].y);
            float2 v1 = make_float2(acc[i][j][2] + bv[j].x, acc[i][j][3] + bv[j].y);
            *reinterpret_cast<float2*>(&Out[(size_t)r * N_TOT + c])       = v0;
            *reinterpret_cast<float2*>(&Out[(size_t)(r + 8) * N_TOT + c]) = v1;
        }
    }
}

// ---------------- launch ----------------
extern "C" void kernel_launch(void* const* d_in, const int* in_sizes, int n_in,
                              void* d_out, int out_size) {
    const float* x    = (const float*)d_in[0];
    const float* W    = (const float*)d_in[1];
    const float* bias = (const float*)d_in[2];
    const float* lA   = (const float*)d_in[3];
    const float* lB   = (const float*)d_in[4];
    float* out = (float*)d_out;
    (void)in_sizes; (void)n_in; (void)out_size;

    prep_kernel<<<CONV_BLOCKS + FOLD_BLOCKS, 256>>>(
        reinterpret_cast<const float4*>(x), W, lA, lB);

    cudaFuncSetAttribute(gemm_kernel,
                         cudaFuncAttributeMaxDynamicSharedMemorySize, SMEM_BYTES);
    gemm_kernel<<<MT * NT, THREADS, SMEM_BYTES>>>(bias, out);
}